// round 13
// baseline (speedup 1.0000x reference)
#include <cuda_runtime.h>
#include <cuda_bf16.h>

#define N_NODES 100000
#define B_DIM   16

// Scratch: transposed x and accumulator, [N, B] layout so one edge's 16
// batch lanes are 64 contiguous bytes.
__device__ float g_xt[N_NODES * B_DIM];
__device__ float g_yt[N_NODES * B_DIM];

#define PDL_LAUNCH_DEPENDENTS() asm volatile("griddepcontrol.launch_dependents;" ::: "memory")
#define PDL_WAIT()              asm volatile("griddepcontrol.wait;" ::: "memory")

// ---------------------------------------------------------------------------
// Kernel 1: transpose x [B,N] -> g_xt [N,B], and zero g_yt (zeroing HERE,
// right before the edge kernel's atomics — proven load-bearing R2 vs R4).
// x read via __ldcs (streamed once; keep L2 young for g_xt/g_yt).
// ---------------------------------------------------------------------------
__global__ void __launch_bounds__(256)
transpose_zero_kernel(const float* __restrict__ x, int N) {
    PDL_LAUNCH_DEPENDENTS();   // edge blocks may start their param preamble

    __shared__ float tile[16][260];
    const int n0 = blockIdx.x * 256;
    const int tid = threadIdx.x;
    const int N4 = N >> 2;

    float4 v[4];
    #pragma unroll
    for (int p = 0; p < 4; p++) {
        int idx = p * 256 + tid;
        int b  = idx >> 6;
        int nq = idx & 63;
        int gq = (n0 >> 2) + nq;
        v[p] = make_float4(0.f, 0.f, 0.f, 0.f);
        if (gq < N4) v[p] = __ldcs(&((const float4*)x)[b * N4 + gq]);
    }
    #pragma unroll
    for (int p = 0; p < 4; p++) {
        int idx = p * 256 + tid;
        int b  = idx >> 6;
        int nq = idx & 63;
        tile[b][4 * nq + 0] = v[p].x;
        tile[b][4 * nq + 1] = v[p].y;
        tile[b][4 * nq + 2] = v[p].z;
        tile[b][4 * nq + 3] = v[p].w;
    }
    __syncthreads();

    #pragma unroll
    for (int p = 0; p < 4; p++) {
        int t = p * 256 + tid;
        int n = t >> 2;
        int q = t & 3;
        int nn = n0 + n;
        if (nn < N) {
            float4 w;
            w.x = tile[4 * q + 0][n];
            w.y = tile[4 * q + 1][n];
            w.z = tile[4 * q + 2][n];
            w.w = tile[4 * q + 3][n];
            *(float4*)&g_xt[nn * B_DIM + 4 * q] = w;
            *(float4*)&g_yt[nn * B_DIM + 4 * q] = make_float4(0.f, 0.f, 0.f, 0.f);
        }
    }
}

// ---------------------------------------------------------------------------
// Kernel 2: edge stage — R7's proven 2-task split-grid body + PDL + __ldcs
// params (R12 win). Block size 512 (fewer CTAs, same occupancy).
// ---------------------------------------------------------------------------
__global__ void __launch_bounds__(512)
edge_kernel(const int*   __restrict__ src_idx,
            const int*   __restrict__ dst_idx,
            const float* __restrict__ edge_alpha,
            const float* __restrict__ edge_w,
            const float* __restrict__ edge_b,
            int E, int half) {
    int t0 = blockIdx.x * blockDim.x + threadIdx.x;
    if (t0 >= half) return;
    int t1 = t0 + half;
    const int T = E * 4;
    bool has1 = (t1 < T);

    int eA = t0 >> 2, qA = t0 & 3;
    int eB = t1 >> 2, qB = t1 & 3;

    // ---- Preamble: param loads only (independent of transpose output) ----
    int   sA = __ldcs(&src_idx[eA]);
    int   dA = __ldcs(&dst_idx[eA]);
    float wA = __ldcs(&edge_w[eA]);
    float bA = __ldcs(&edge_b[eA]);
    float aA = __ldcs(&edge_alpha[eA]);

    int eBs = has1 ? eB : eA;
    int   sB = __ldcs(&src_idx[eBs]);
    int   dB = __ldcs(&dst_idx[eBs]);
    float wB = __ldcs(&edge_w[eBs]);
    float bB = __ldcs(&edge_b[eBs]);
    float aB = __ldcs(&edge_alpha[eBs]);

    PDL_LAUNCH_DEPENDENTS();
    PDL_WAIT();                // transpose complete + writes visible

    // ---- Two independent gathers in flight ----
    float4 xA = __ldg((const float4*)&g_xt[sA * B_DIM + 4 * qA]);
    float4 xB = __ldg((const float4*)&g_xt[sB * B_DIM + 4 * qB]);

    // Task A math + RED
    {
        float l0 = fmaf(wA, xA.x, bA);
        float l1 = fmaf(wA, xA.y, bA);
        float l2 = fmaf(wA, xA.z, bA);
        float l3 = fmaf(wA, xA.w, bA);
        float h0, h1, h2, h3;
        asm("tanh.approx.f32 %0, %1;" : "=f"(h0) : "f"(l0));
        asm("tanh.approx.f32 %0, %1;" : "=f"(h1) : "f"(l1));
        asm("tanh.approx.f32 %0, %1;" : "=f"(h2) : "f"(l2));
        asm("tanh.approx.f32 %0, %1;" : "=f"(h3) : "f"(l3));
        float m0 = fmaf(aA, h0 - l0, l0);
        float m1 = fmaf(aA, h1 - l1, l1);
        float m2 = fmaf(aA, h2 - l2, l2);
        float m3 = fmaf(aA, h3 - l3, l3);
        size_t gaddr = __cvta_generic_to_global(&g_yt[dA * B_DIM + 4 * qA]);
        asm volatile("red.global.add.v4.f32 [%0], {%1, %2, %3, %4};"
                     :: "l"(gaddr), "f"(m0), "f"(m1), "f"(m2), "f"(m3)
                     : "memory");
    }

    // Task B math + RED
    if (has1) {
        float l0 = fmaf(wB, xB.x, bB);
        float l1 = fmaf(wB, xB.y, bB);
        float l2 = fmaf(wB, xB.z, bB);
        float l3 = fmaf(wB, xB.w, bB);
        float h0, h1, h2, h3;
        asm("tanh.approx.f32 %0, %1;" : "=f"(h0) : "f"(l0));
        asm("tanh.approx.f32 %0, %1;" : "=f"(h1) : "f"(l1));
        asm("tanh.approx.f32 %0, %1;" : "=f"(h2) : "f"(l2));
        asm("tanh.approx.f32 %0, %1;" : "=f"(h3) : "f"(l3));
        float m0 = fmaf(aB, h0 - l0, l0);
        float m1 = fmaf(aB, h1 - l1, l1);
        float m2 = fmaf(aB, h2 - l2, l2);
        float m3 = fmaf(aB, h3 - l3, l3);
        size_t gaddr = __cvta_generic_to_global(&g_yt[dB * B_DIM + 4 * qB]);
        asm volatile("red.global.add.v4.f32 [%0], {%1, %2, %3, %4};"
                     :: "l"(gaddr), "f"(m0), "f"(m1), "f"(m2), "f"(m3)
                     : "memory");
    }
}

// ---------------------------------------------------------------------------
// Kernel 3: node stage + transpose back (R10 form; params via __ldcs).
// ---------------------------------------------------------------------------
__global__ void __launch_bounds__(256)
node_kernel(const float* __restrict__ node_alpha,
            const float* __restrict__ node_w,
            const float* __restrict__ node_b,
            float* __restrict__ out, int N) {
    __shared__ float tile[16][260];
    __shared__ float s_w[256], s_b[256], s_a[256];
    const int n0 = blockIdx.x * 256;
    const int tid = threadIdx.x;
    const int N4 = N >> 2;

    // ---- Preamble: node params for this tile (independent of edge) ----
    {
        int nn = n0 + tid;
        float w = 0.f, b = 0.f, a = 0.f;
        if (nn < N) {
            w = __ldcs(&node_w[nn]);
            b = __ldcs(&node_b[nn]);
            a = __ldcs(&node_alpha[nn]);
        }
        s_w[tid] = w; s_b[tid] = b; s_a[tid] = a;
    }
    __syncthreads();

    PDL_WAIT();   // edge complete; all REDs to g_yt visible

    float4 v[4];
    #pragma unroll
    for (int p = 0; p < 4; p++) {
        int t = p * 256 + tid;
        int n = t >> 2;
        int q = t & 3;
        int nn = n0 + n;
        v[p] = make_float4(0.f, 0.f, 0.f, 0.f);
        if (nn < N) v[p] = *(const float4*)&g_yt[nn * B_DIM + 4 * q];
    }
    #pragma unroll
    for (int p = 0; p < 4; p++) {
        int t = p * 256 + tid;
        int n = t >> 2;
        int q = t & 3;
        tile[4 * q + 0][n] = v[p].x;
        tile[4 * q + 1][n] = v[p].y;
        tile[4 * q + 2][n] = v[p].z;
        tile[4 * q + 3][n] = v[p].w;
    }
    __syncthreads();

    #pragma unroll
    for (int p = 0; p < 4; p++) {
        int idx = p * 256 + tid;
        int b  = idx >> 6;
        int nq = idx & 63;
        int gq = (n0 >> 2) + nq;
        if (gq < N4) {
            float4 r;
            #pragma unroll
            for (int k = 0; k < 4; k++) {
                int nl = 4 * nq + k;
                float y   = tile[b][nl];
                float lin = fmaf(s_w[nl], y, s_b[nl]);
                float th;
                asm("tanh.approx.f32 %0, %1;" : "=f"(th) : "f"(lin));
                ((float*)&r)[k] = fmaf(s_a[nl], th - lin, lin);
            }
            ((float4*)out)[b * N4 + gq] = r;
        }
    }
}

// ---------------------------------------------------------------------------
// Input order: x, src_idx, dst_idx, edge_alpha, edge_w, edge_b,
// node_alpha, node_w, node_b. Output: float32 [B, N].
// ---------------------------------------------------------------------------
extern "C" void kernel_launch(void* const* d_in, const int* in_sizes, int n_in,
                              void* d_out, int out_size) {
    const float* x          = (const float*)d_in[0];
    const int*   src_idx    = (const int*)  d_in[1];
    const int*   dst_idx    = (const int*)  d_in[2];
    const float* edge_alpha = (const float*)d_in[3];
    const float* edge_w     = (const float*)d_in[4];
    const float* edge_b     = (const float*)d_in[5];
    const float* node_alpha = (const float*)d_in[6];
    const float* node_w     = (const float*)d_in[7];
    const float* node_b     = (const float*)d_in[8];
    float* out = (float*)d_out;

    const int E = in_sizes[1];
    const int N = in_sizes[6];

    const int n_tiles = (N + 255) / 256;

    // K1: transpose (256-node tiles).
    transpose_zero_kernel<<<n_tiles, 256>>>(x, N);

    cudaLaunchAttribute pdl_attr[1];
    pdl_attr[0].id = cudaLaunchAttributeProgrammaticStreamSerialization;
    pdl_attr[0].val.programmaticStreamSerializationAllowed = 1;

    // K2: edge, PDL-dependent on transpose. Block 512.
    {
        const int T = E * 4;
        int half = ((T + 1) / 2 + 511) & ~511;
        cudaLaunchConfig_t cfg = {};
        cfg.gridDim  = dim3(half / 512, 1, 1);
        cfg.blockDim = dim3(512, 1, 1);
        cfg.dynamicSmemBytes = 0;
        cfg.stream = 0;
        cfg.attrs = pdl_attr;
        cfg.numAttrs = 1;
        cudaLaunchKernelEx(&cfg, edge_kernel, src_idx, dst_idx, edge_alpha,
                           edge_w, edge_b, E, half);
    }

    // K3: node, PDL-dependent on edge.
    {
        cudaLaunchConfig_t cfg = {};
        cfg.gridDim  = dim3(n_tiles, 1, 1);
        cfg.blockDim = dim3(256, 1, 1);
        cfg.dynamicSmemBytes = 0;
        cfg.stream = 0;
        cfg.attrs = pdl_attr;
        cfg.numAttrs = 1;
        cudaLaunchKernelEx(&cfg, node_kernel, node_alpha, node_w, node_b,
                           out, N);
    }
}

// round 14
// speedup vs baseline: 1.0374x; 1.0374x over previous
#include <cuda_runtime.h>
#include <cuda_bf16.h>

#define N_NODES 100000
#define B_DIM   16

// Scratch: transposed x and accumulator, [N, B] layout so one edge's 16
// batch lanes are 64 contiguous bytes.
__device__ float g_xt[N_NODES * B_DIM];
__device__ float g_yt[N_NODES * B_DIM];

#define PDL_LAUNCH_DEPENDENTS() asm volatile("griddepcontrol.launch_dependents;" ::: "memory")
#define PDL_WAIT()              asm volatile("griddepcontrol.wait;" ::: "memory")

// ---------------------------------------------------------------------------
// Kernel 1: transpose x [B,N] -> g_xt [N,B], and zero g_yt (zeroing HERE,
// right before the edge kernel's atomics — proven load-bearing R2 vs R4).
// 256-node tile, plain float4 loads (R13 showed __ldcs on x regresses).
// ---------------------------------------------------------------------------
__global__ void __launch_bounds__(256)
transpose_zero_kernel(const float* __restrict__ x, int N) {
    PDL_LAUNCH_DEPENDENTS();   // edge blocks may start their param preamble

    __shared__ float tile[16][260];
    const int n0 = blockIdx.x * 256;
    const int tid = threadIdx.x;
    const int N4 = N >> 2;

    float4 v[4];
    #pragma unroll
    for (int p = 0; p < 4; p++) {
        int idx = p * 256 + tid;
        int b  = idx >> 6;
        int nq = idx & 63;
        int gq = (n0 >> 2) + nq;
        v[p] = make_float4(0.f, 0.f, 0.f, 0.f);
        if (gq < N4) v[p] = ((const float4*)x)[b * N4 + gq];
    }
    #pragma unroll
    for (int p = 0; p < 4; p++) {
        int idx = p * 256 + tid;
        int b  = idx >> 6;
        int nq = idx & 63;
        tile[b][4 * nq + 0] = v[p].x;
        tile[b][4 * nq + 1] = v[p].y;
        tile[b][4 * nq + 2] = v[p].z;
        tile[b][4 * nq + 3] = v[p].w;
    }
    __syncthreads();

    #pragma unroll
    for (int p = 0; p < 4; p++) {
        int t = p * 256 + tid;
        int n = t >> 2;
        int q = t & 3;
        int nn = n0 + n;
        if (nn < N) {
            float4 w;
            w.x = tile[4 * q + 0][n];
            w.y = tile[4 * q + 1][n];
            w.z = tile[4 * q + 2][n];
            w.w = tile[4 * q + 3][n];
            *(float4*)&g_xt[nn * B_DIM + 4 * q] = w;
            *(float4*)&g_yt[nn * B_DIM + 4 * q] = make_float4(0.f, 0.f, 0.f, 0.f);
        }
    }
}

// ---------------------------------------------------------------------------
// Kernel 2: edge stage — 2-task split-grid body + PDL. __ldcs on the
// once-streamed params (R12 win); block 256, natural register allocation
// (forced occupancy and block 512 both measured worse).
// ---------------------------------------------------------------------------
__global__ void __launch_bounds__(256)
edge_kernel(const int*   __restrict__ src_idx,
            const int*   __restrict__ dst_idx,
            const float* __restrict__ edge_alpha,
            const float* __restrict__ edge_w,
            const float* __restrict__ edge_b,
            int E, int half) {
    int t0 = blockIdx.x * blockDim.x + threadIdx.x;
    if (t0 >= half) return;
    int t1 = t0 + half;
    const int T = E * 4;
    bool has1 = (t1 < T);

    int eA = t0 >> 2, qA = t0 & 3;
    int eB = t1 >> 2, qB = t1 & 3;

    // ---- Preamble: param loads only (independent of transpose output) ----
    int   sA = __ldcs(&src_idx[eA]);
    int   dA = __ldcs(&dst_idx[eA]);
    float wA = __ldcs(&edge_w[eA]);
    float bA = __ldcs(&edge_b[eA]);
    float aA = __ldcs(&edge_alpha[eA]);

    int eBs = has1 ? eB : eA;
    int   sB = __ldcs(&src_idx[eBs]);
    int   dB = __ldcs(&dst_idx[eBs]);
    float wB = __ldcs(&edge_w[eBs]);
    float bB = __ldcs(&edge_b[eBs]);
    float aB = __ldcs(&edge_alpha[eBs]);

    PDL_LAUNCH_DEPENDENTS();
    PDL_WAIT();                // transpose complete + writes visible

    // ---- Two independent gathers in flight ----
    float4 xA = __ldg((const float4*)&g_xt[sA * B_DIM + 4 * qA]);
    float4 xB = __ldg((const float4*)&g_xt[sB * B_DIM + 4 * qB]);

    // Task A math + RED
    {
        float l0 = fmaf(wA, xA.x, bA);
        float l1 = fmaf(wA, xA.y, bA);
        float l2 = fmaf(wA, xA.z, bA);
        float l3 = fmaf(wA, xA.w, bA);
        float h0, h1, h2, h3;
        asm("tanh.approx.f32 %0, %1;" : "=f"(h0) : "f"(l0));
        asm("tanh.approx.f32 %0, %1;" : "=f"(h1) : "f"(l1));
        asm("tanh.approx.f32 %0, %1;" : "=f"(h2) : "f"(l2));
        asm("tanh.approx.f32 %0, %1;" : "=f"(h3) : "f"(l3));
        float m0 = fmaf(aA, h0 - l0, l0);
        float m1 = fmaf(aA, h1 - l1, l1);
        float m2 = fmaf(aA, h2 - l2, l2);
        float m3 = fmaf(aA, h3 - l3, l3);
        size_t gaddr = __cvta_generic_to_global(&g_yt[dA * B_DIM + 4 * qA]);
        asm volatile("red.global.add.v4.f32 [%0], {%1, %2, %3, %4};"
                     :: "l"(gaddr), "f"(m0), "f"(m1), "f"(m2), "f"(m3)
                     : "memory");
    }

    // Task B math + RED
    if (has1) {
        float l0 = fmaf(wB, xB.x, bB);
        float l1 = fmaf(wB, xB.y, bB);
        float l2 = fmaf(wB, xB.z, bB);
        float l3 = fmaf(wB, xB.w, bB);
        float h0, h1, h2, h3;
        asm("tanh.approx.f32 %0, %1;" : "=f"(h0) : "f"(l0));
        asm("tanh.approx.f32 %0, %1;" : "=f"(h1) : "f"(l1));
        asm("tanh.approx.f32 %0, %1;" : "=f"(h2) : "f"(l2));
        asm("tanh.approx.f32 %0, %1;" : "=f"(h3) : "f"(l3));
        float m0 = fmaf(aB, h0 - l0, l0);
        float m1 = fmaf(aB, h1 - l1, l1);
        float m2 = fmaf(aB, h2 - l2, l2);
        float m3 = fmaf(aB, h3 - l3, l3);
        size_t gaddr = __cvta_generic_to_global(&g_yt[dB * B_DIM + 4 * qB]);
        asm volatile("red.global.add.v4.f32 [%0], {%1, %2, %3, %4};"
                     :: "l"(gaddr), "f"(m0), "f"(m1), "f"(m2), "f"(m3)
                     : "memory");
    }
}

// ---------------------------------------------------------------------------
// Kernel 3: node stage + transpose back (smem param preamble + PDL; plain
// __ldg on params — R13's __ldcs variant regressed).
// ---------------------------------------------------------------------------
__global__ void __launch_bounds__(256)
node_kernel(const float* __restrict__ node_alpha,
            const float* __restrict__ node_w,
            const float* __restrict__ node_b,
            float* __restrict__ out, int N) {
    __shared__ float tile[16][260];
    __shared__ float s_w[256], s_b[256], s_a[256];
    const int n0 = blockIdx.x * 256;
    const int tid = threadIdx.x;
    const int N4 = N >> 2;

    // ---- Preamble: node params for this tile (independent of edge) ----
    {
        int nn = n0 + tid;
        float w = 0.f, b = 0.f, a = 0.f;
        if (nn < N) {
            w = __ldg(&node_w[nn]);
            b = __ldg(&node_b[nn]);
            a = __ldg(&node_alpha[nn]);
        }
        s_w[tid] = w; s_b[tid] = b; s_a[tid] = a;
    }
    __syncthreads();

    PDL_WAIT();   // edge complete; all REDs to g_yt visible

    float4 v[4];
    #pragma unroll
    for (int p = 0; p < 4; p++) {
        int t = p * 256 + tid;
        int n = t >> 2;
        int q = t & 3;
        int nn = n0 + n;
        v[p] = make_float4(0.f, 0.f, 0.f, 0.f);
        if (nn < N) v[p] = *(const float4*)&g_yt[nn * B_DIM + 4 * q];
    }
    #pragma unroll
    for (int p = 0; p < 4; p++) {
        int t = p * 256 + tid;
        int n = t >> 2;
        int q = t & 3;
        tile[4 * q + 0][n] = v[p].x;
        tile[4 * q + 1][n] = v[p].y;
        tile[4 * q + 2][n] = v[p].z;
        tile[4 * q + 3][n] = v[p].w;
    }
    __syncthreads();

    #pragma unroll
    for (int p = 0; p < 4; p++) {
        int idx = p * 256 + tid;
        int b  = idx >> 6;
        int nq = idx & 63;
        int gq = (n0 >> 2) + nq;
        if (gq < N4) {
            float4 r;
            #pragma unroll
            for (int k = 0; k < 4; k++) {
                int nl = 4 * nq + k;
                float y   = tile[b][nl];
                float lin = fmaf(s_w[nl], y, s_b[nl]);
                float th;
                asm("tanh.approx.f32 %0, %1;" : "=f"(th) : "f"(lin));
                ((float*)&r)[k] = fmaf(s_a[nl], th - lin, lin);
            }
            ((float4*)out)[b * N4 + gq] = r;
        }
    }
}

// ---------------------------------------------------------------------------
// Input order: x, src_idx, dst_idx, edge_alpha, edge_w, edge_b,
// node_alpha, node_w, node_b. Output: float32 [B, N].
// ---------------------------------------------------------------------------
extern "C" void kernel_launch(void* const* d_in, const int* in_sizes, int n_in,
                              void* d_out, int out_size) {
    const float* x          = (const float*)d_in[0];
    const int*   src_idx    = (const int*)  d_in[1];
    const int*   dst_idx    = (const int*)  d_in[2];
    const float* edge_alpha = (const float*)d_in[3];
    const float* edge_w     = (const float*)d_in[4];
    const float* edge_b     = (const float*)d_in[5];
    const float* node_alpha = (const float*)d_in[6];
    const float* node_w     = (const float*)d_in[7];
    const float* node_b     = (const float*)d_in[8];
    float* out = (float*)d_out;

    const int E = in_sizes[1];
    const int N = in_sizes[6];

    const int n_tiles = (N + 255) / 256;

    // K1: transpose (256-node tiles).
    transpose_zero_kernel<<<n_tiles, 256>>>(x, N);

    cudaLaunchAttribute pdl_attr[1];
    pdl_attr[0].id = cudaLaunchAttributeProgrammaticStreamSerialization;
    pdl_attr[0].val.programmaticStreamSerializationAllowed = 1;

    // K2: edge, PDL-dependent on transpose.
    {
        const int T = E * 4;
        int half = ((T + 1) / 2 + 255) & ~255;
        cudaLaunchConfig_t cfg = {};
        cfg.gridDim  = dim3(half / 256, 1, 1);
        cfg.blockDim = dim3(256, 1, 1);
        cfg.dynamicSmemBytes = 0;
        cfg.stream = 0;
        cfg.attrs = pdl_attr;
        cfg.numAttrs = 1;
        cudaLaunchKernelEx(&cfg, edge_kernel, src_idx, dst_idx, edge_alpha,
                           edge_w, edge_b, E, half);
    }

    // K3: node, PDL-dependent on edge.
    {
        cudaLaunchConfig_t cfg = {};
        cfg.gridDim  = dim3(n_tiles, 1, 1);
        cfg.blockDim = dim3(256, 1, 1);
        cfg.dynamicSmemBytes = 0;
        cfg.stream = 0;
        cfg.attrs = pdl_attr;
        cfg.numAttrs = 1;
        cudaLaunchKernelEx(&cfg, node_kernel, node_alpha, node_w, node_b,
                           out, N);
    }
}

// round 15
// speedup vs baseline: 1.0379x; 1.0005x over previous
#include <cuda_runtime.h>
#include <cuda_bf16.h>

#define N_NODES 100000
#define B_DIM   16

// Scratch: transposed x and accumulator, [N, B] layout so one edge's 16
// batch lanes are 64 contiguous bytes.
__device__ float g_xt[N_NODES * B_DIM];
__device__ float g_yt[N_NODES * B_DIM];

#define PDL_LAUNCH_DEPENDENTS() asm volatile("griddepcontrol.launch_dependents;" ::: "memory")
#define PDL_WAIT()              asm volatile("griddepcontrol.wait;" ::: "memory")

// ---------------------------------------------------------------------------
// Kernel 1: transpose x [B,N] -> g_xt [N,B], and zero g_yt (zeroing HERE,
// right before the edge kernel's atomics — proven load-bearing R2 vs R4).
// 256-node tile, plain float4 loads (R13 showed __ldcs on x regresses).
// ---------------------------------------------------------------------------
__global__ void __launch_bounds__(256)
transpose_zero_kernel(const float* __restrict__ x, int N) {
    PDL_LAUNCH_DEPENDENTS();   // edge blocks may start their param preamble

    __shared__ float tile[16][260];
    const int n0 = blockIdx.x * 256;
    const int tid = threadIdx.x;
    const int N4 = N >> 2;

    float4 v[4];
    #pragma unroll
    for (int p = 0; p < 4; p++) {
        int idx = p * 256 + tid;
        int b  = idx >> 6;
        int nq = idx & 63;
        int gq = (n0 >> 2) + nq;
        v[p] = make_float4(0.f, 0.f, 0.f, 0.f);
        if (gq < N4) v[p] = ((const float4*)x)[b * N4 + gq];
    }
    #pragma unroll
    for (int p = 0; p < 4; p++) {
        int idx = p * 256 + tid;
        int b  = idx >> 6;
        int nq = idx & 63;
        tile[b][4 * nq + 0] = v[p].x;
        tile[b][4 * nq + 1] = v[p].y;
        tile[b][4 * nq + 2] = v[p].z;
        tile[b][4 * nq + 3] = v[p].w;
    }
    __syncthreads();

    #pragma unroll
    for (int p = 0; p < 4; p++) {
        int t = p * 256 + tid;
        int n = t >> 2;
        int q = t & 3;
        int nn = n0 + n;
        if (nn < N) {
            float4 w;
            w.x = tile[4 * q + 0][n];
            w.y = tile[4 * q + 1][n];
            w.z = tile[4 * q + 2][n];
            w.w = tile[4 * q + 3][n];
            *(float4*)&g_xt[nn * B_DIM + 4 * q] = w;
            *(float4*)&g_yt[nn * B_DIM + 4 * q] = make_float4(0.f, 0.f, 0.f, 0.f);
        }
    }
}

// ---------------------------------------------------------------------------
// Kernel 2: edge stage — 2-task split-grid body + PDL. __ldcs on the
// once-streamed params (R12 win); block 256, natural register allocation
// (forced occupancy and block 512 both measured worse).
// ---------------------------------------------------------------------------
__global__ void __launch_bounds__(256)
edge_kernel(const int*   __restrict__ src_idx,
            const int*   __restrict__ dst_idx,
            const float* __restrict__ edge_alpha,
            const float* __restrict__ edge_w,
            const float* __restrict__ edge_b,
            int E, int half) {
    int t0 = blockIdx.x * blockDim.x + threadIdx.x;
    if (t0 >= half) return;
    int t1 = t0 + half;
    const int T = E * 4;
    bool has1 = (t1 < T);

    int eA = t0 >> 2, qA = t0 & 3;
    int eB = t1 >> 2, qB = t1 & 3;

    // ---- Preamble: param loads only (independent of transpose output) ----
    int   sA = __ldcs(&src_idx[eA]);
    int   dA = __ldcs(&dst_idx[eA]);
    float wA = __ldcs(&edge_w[eA]);
    float bA = __ldcs(&edge_b[eA]);
    float aA = __ldcs(&edge_alpha[eA]);

    int eBs = has1 ? eB : eA;
    int   sB = __ldcs(&src_idx[eBs]);
    int   dB = __ldcs(&dst_idx[eBs]);
    float wB = __ldcs(&edge_w[eBs]);
    float bB = __ldcs(&edge_b[eBs]);
    float aB = __ldcs(&edge_alpha[eBs]);

    PDL_LAUNCH_DEPENDENTS();
    PDL_WAIT();                // transpose complete + writes visible

    // ---- Two independent gathers in flight ----
    float4 xA = __ldg((const float4*)&g_xt[sA * B_DIM + 4 * qA]);
    float4 xB = __ldg((const float4*)&g_xt[sB * B_DIM + 4 * qB]);

    // Task A math + RED
    {
        float l0 = fmaf(wA, xA.x, bA);
        float l1 = fmaf(wA, xA.y, bA);
        float l2 = fmaf(wA, xA.z, bA);
        float l3 = fmaf(wA, xA.w, bA);
        float h0, h1, h2, h3;
        asm("tanh.approx.f32 %0, %1;" : "=f"(h0) : "f"(l0));
        asm("tanh.approx.f32 %0, %1;" : "=f"(h1) : "f"(l1));
        asm("tanh.approx.f32 %0, %1;" : "=f"(h2) : "f"(l2));
        asm("tanh.approx.f32 %0, %1;" : "=f"(h3) : "f"(l3));
        float m0 = fmaf(aA, h0 - l0, l0);
        float m1 = fmaf(aA, h1 - l1, l1);
        float m2 = fmaf(aA, h2 - l2, l2);
        float m3 = fmaf(aA, h3 - l3, l3);
        size_t gaddr = __cvta_generic_to_global(&g_yt[dA * B_DIM + 4 * qA]);
        asm volatile("red.global.add.v4.f32 [%0], {%1, %2, %3, %4};"
                     :: "l"(gaddr), "f"(m0), "f"(m1), "f"(m2), "f"(m3)
                     : "memory");
    }

    // Task B math + RED
    if (has1) {
        float l0 = fmaf(wB, xB.x, bB);
        float l1 = fmaf(wB, xB.y, bB);
        float l2 = fmaf(wB, xB.z, bB);
        float l3 = fmaf(wB, xB.w, bB);
        float h0, h1, h2, h3;
        asm("tanh.approx.f32 %0, %1;" : "=f"(h0) : "f"(l0));
        asm("tanh.approx.f32 %0, %1;" : "=f"(h1) : "f"(l1));
        asm("tanh.approx.f32 %0, %1;" : "=f"(h2) : "f"(l2));
        asm("tanh.approx.f32 %0, %1;" : "=f"(h3) : "f"(l3));
        float m0 = fmaf(aB, h0 - l0, l0);
        float m1 = fmaf(aB, h1 - l1, l1);
        float m2 = fmaf(aB, h2 - l2, l2);
        float m3 = fmaf(aB, h3 - l3, l3);
        size_t gaddr = __cvta_generic_to_global(&g_yt[dB * B_DIM + 4 * qB]);
        asm volatile("red.global.add.v4.f32 [%0], {%1, %2, %3, %4};"
                     :: "l"(gaddr), "f"(m0), "f"(m1), "f"(m2), "f"(m3)
                     : "memory");
    }
}

// ---------------------------------------------------------------------------
// Kernel 3: node stage + transpose back (smem param preamble + PDL; plain
// __ldg on params — R13's __ldcs variant regressed).
// ---------------------------------------------------------------------------
__global__ void __launch_bounds__(256)
node_kernel(const float* __restrict__ node_alpha,
            const float* __restrict__ node_w,
            const float* __restrict__ node_b,
            float* __restrict__ out, int N) {
    __shared__ float tile[16][260];
    __shared__ float s_w[256], s_b[256], s_a[256];
    const int n0 = blockIdx.x * 256;
    const int tid = threadIdx.x;
    const int N4 = N >> 2;

    // ---- Preamble: node params for this tile (independent of edge) ----
    {
        int nn = n0 + tid;
        float w = 0.f, b = 0.f, a = 0.f;
        if (nn < N) {
            w = __ldg(&node_w[nn]);
            b = __ldg(&node_b[nn]);
            a = __ldg(&node_alpha[nn]);
        }
        s_w[tid] = w; s_b[tid] = b; s_a[tid] = a;
    }
    __syncthreads();

    PDL_WAIT();   // edge complete; all REDs to g_yt visible

    float4 v[4];
    #pragma unroll
    for (int p = 0; p < 4; p++) {
        int t = p * 256 + tid;
        int n = t >> 2;
        int q = t & 3;
        int nn = n0 + n;
        v[p] = make_float4(0.f, 0.f, 0.f, 0.f);
        if (nn < N) v[p] = *(const float4*)&g_yt[nn * B_DIM + 4 * q];
    }
    #pragma unroll
    for (int p = 0; p < 4; p++) {
        int t = p * 256 + tid;
        int n = t >> 2;
        int q = t & 3;
        tile[4 * q + 0][n] = v[p].x;
        tile[4 * q + 1][n] = v[p].y;
        tile[4 * q + 2][n] = v[p].z;
        tile[4 * q + 3][n] = v[p].w;
    }
    __syncthreads();

    #pragma unroll
    for (int p = 0; p < 4; p++) {
        int idx = p * 256 + tid;
        int b  = idx >> 6;
        int nq = idx & 63;
        int gq = (n0 >> 2) + nq;
        if (gq < N4) {
            float4 r;
            #pragma unroll
            for (int k = 0; k < 4; k++) {
                int nl = 4 * nq + k;
                float y   = tile[b][nl];
                float lin = fmaf(s_w[nl], y, s_b[nl]);
                float th;
                asm("tanh.approx.f32 %0, %1;" : "=f"(th) : "f"(lin));
                ((float*)&r)[k] = fmaf(s_a[nl], th - lin, lin);
            }
            ((float4*)out)[b * N4 + gq] = r;
        }
    }
}

// ---------------------------------------------------------------------------
// Input order: x, src_idx, dst_idx, edge_alpha, edge_w, edge_b,
// node_alpha, node_w, node_b. Output: float32 [B, N].
// ---------------------------------------------------------------------------
extern "C" void kernel_launch(void* const* d_in, const int* in_sizes, int n_in,
                              void* d_out, int out_size) {
    const float* x          = (const float*)d_in[0];
    const int*   src_idx    = (const int*)  d_in[1];
    const int*   dst_idx    = (const int*)  d_in[2];
    const float* edge_alpha = (const float*)d_in[3];
    const float* edge_w     = (const float*)d_in[4];
    const float* edge_b     = (const float*)d_in[5];
    const float* node_alpha = (const float*)d_in[6];
    const float* node_w     = (const float*)d_in[7];
    const float* node_b     = (const float*)d_in[8];
    float* out = (float*)d_out;

    const int E = in_sizes[1];
    const int N = in_sizes[6];

    const int n_tiles = (N + 255) / 256;

    // K1: transpose (256-node tiles).
    transpose_zero_kernel<<<n_tiles, 256>>>(x, N);

    cudaLaunchAttribute pdl_attr[1];
    pdl_attr[0].id = cudaLaunchAttributeProgrammaticStreamSerialization;
    pdl_attr[0].val.programmaticStreamSerializationAllowed = 1;

    // K2: edge, PDL-dependent on transpose.
    {
        const int T = E * 4;
        int half = ((T + 1) / 2 + 255) & ~255;
        cudaLaunchConfig_t cfg = {};
        cfg.gridDim  = dim3(half / 256, 1, 1);
        cfg.blockDim = dim3(256, 1, 1);
        cfg.dynamicSmemBytes = 0;
        cfg.stream = 0;
        cfg.attrs = pdl_attr;
        cfg.numAttrs = 1;
        cudaLaunchKernelEx(&cfg, edge_kernel, src_idx, dst_idx, edge_alpha,
                           edge_w, edge_b, E, half);
    }

    // K3: node, PDL-dependent on edge.
    {
        cudaLaunchConfig_t cfg = {};
        cfg.gridDim  = dim3(n_tiles, 1, 1);
        cfg.blockDim = dim3(256, 1, 1);
        cfg.dynamicSmemBytes = 0;
        cfg.stream = 0;
        cfg.attrs = pdl_attr;
        cfg.numAttrs = 1;
        cudaLaunchKernelEx(&cfg, node_kernel, node_alpha, node_w, node_b,
                           out, N);
    }
}